// round 1
// baseline (speedup 1.0000x reference)
#include <cuda_runtime.h>
#include <math.h>

// Problem constants
#define NTOK 2048      // B*S tokens
#define DIM  1024      // embed dim
#define FF   4096      // expert intermediate
#define FSH  2048      // shared intermediate
#define NE   8         // experts
#define TOPK 2
#define NSLOT (NTOK*TOPK)   // 4096 routed assignments

// GEMM tiling
#define BM 64
#define BN 128
#define BK 16
#define TM 4
#define TN 8
// 256 threads: tx = t & 15 (N dir, 8 cols each), ty = t >> 4 (M dir, 4 rows each)

// ---- scratch (static device globals; no allocation) ----
__device__ float g_act[(size_t)NSLOT * FF];    // 64 MB swiglu activations (slot-major, weighted)
__device__ float g_eo[(size_t)NSLOT * DIM];    // 16 MB routed down-proj outputs, indexed tok*2+k
__device__ float g_hs[(size_t)NTOK * FSH];     // 16 MB shared-expert intermediate
__device__ float g_topw[NTOK * TOPK];
__device__ int   g_topi[NTOK * TOPK];
__device__ int   g_slot_tok[NSLOT];
__device__ float g_slot_w[NSLOT];
__device__ int   g_slot_dst[NSLOT];
__device__ int   g_cnt[NE];
__device__ int   g_off[NE + 1];

// ---------------------------------------------------------------------------
// Router: logits = x @ gate_w^T, softmax, top-2. One block per token.
// ---------------------------------------------------------------------------
__global__ void router_kernel(const float* __restrict__ x,
                              const float* __restrict__ gate_w)
{
    const int n = blockIdx.x;
    const int tid = threadIdx.x;
    __shared__ float sred[NE][128];

    float acc[NE];
#pragma unroll
    for (int e = 0; e < NE; e++) acc[e] = 0.f;

    const float* xr = x + (size_t)n * DIM;
    for (int d = tid; d < DIM; d += 128) {
        float xv = xr[d];
#pragma unroll
        for (int e = 0; e < NE; e++)
            acc[e] = fmaf(xv, gate_w[e * DIM + d], acc[e]);
    }
#pragma unroll
    for (int e = 0; e < NE; e++) sred[e][tid] = acc[e];
    __syncthreads();

    if (tid < NE) {
        float s = 0.f;
        for (int i = 0; i < 128; i++) s += sred[tid][i];   // deterministic order
        sred[tid][0] = s;
    }
    __syncthreads();

    if (tid == 0) {
        float lg[NE];
#pragma unroll
        for (int e = 0; e < NE; e++) lg[e] = sred[e][0];
        float mx = lg[0];
#pragma unroll
        for (int e = 1; e < NE; e++) mx = fmaxf(mx, lg[e]);
        float se = 0.f, p[NE];
#pragma unroll
        for (int e = 0; e < NE; e++) { p[e] = expf(lg[e] - mx); se += p[e]; }
        float inv = 1.f / se;
#pragma unroll
        for (int e = 0; e < NE; e++) p[e] *= inv;

        int i1 = 0; float v1 = p[0];
#pragma unroll
        for (int e = 1; e < NE; e++) if (p[e] > v1) { v1 = p[e]; i1 = e; }
        int i2 = -1; float v2 = -1.f;
#pragma unroll
        for (int e = 0; e < NE; e++) if (e != i1 && p[e] > v2) { v2 = p[e]; i2 = e; }

        g_topi[n * 2 + 0] = i1;  g_topw[n * 2 + 0] = v1;
        g_topi[n * 2 + 1] = i2;  g_topw[n * 2 + 1] = v2;
        atomicAdd(&g_cnt[i1], 1);
        atomicAdd(&g_cnt[i2], 1);
    }
}

__global__ void zero_cnt_kernel()
{
    if (threadIdx.x < NE) g_cnt[threadIdx.x] = 0;
}

__global__ void scan_kernel()
{
    if (threadIdx.x == 0) {
        int r = 0;
        for (int e = 0; e < NE; e++) { g_off[e] = r; r += g_cnt[e]; g_cnt[e] = 0; }
        g_off[NE] = r;
    }
}

__global__ void fill_kernel()
{
    int n = blockIdx.x * blockDim.x + threadIdx.x;
    if (n >= NTOK) return;
#pragma unroll
    for (int k = 0; k < TOPK; k++) {
        int e = g_topi[n * 2 + k];
        int pos = atomicAdd(&g_cnt[e], 1);
        int slot = g_off[e] + pos;
        g_slot_tok[slot] = n;
        g_slot_w[slot]   = g_topw[n * 2 + k];
        g_slot_dst[slot] = n * 2 + k;
    }
}

// ---------------------------------------------------------------------------
// Routed gate+up fused GEMM + SwiGLU + routing weight.
// A = gathered x rows [cnt_e, DIM], Bg/Bu = gate_k[e]/up_k[e] [DIM, FF].
// Out: g_act[slot, FF] = w * silu(g) * u
// ---------------------------------------------------------------------------
__global__ __launch_bounds__(256)
void gemm_gateup_routed(const float* __restrict__ x,
                        const float* __restrict__ gate_k,
                        const float* __restrict__ up_k)
{
    const int e = blockIdx.z;
    const int cnt = g_cnt[e];
    const int rowbase = blockIdx.y * BM;
    if (rowbase >= cnt) return;
    const int off = g_off[e];
    const int n0 = blockIdx.x * BN;
    const float* __restrict__ Bg = gate_k + (size_t)e * DIM * FF;
    const float* __restrict__ Bu = up_k   + (size_t)e * DIM * FF;

    __shared__ float As[BK][68];
    __shared__ float Bgs[BK][BN];
    __shared__ float Bus[BK][BN];

    const int t = threadIdx.x;
    const int tx = t & 15, ty = t >> 4;
    const int tn0 = tx * TN, tm0 = ty * TM;

    const int a_row = t >> 2, a_seg = t & 3;
    int m_g = rowbase + a_row;
    if (m_g >= cnt) m_g = cnt - 1;
    const float* a_src = x + (size_t)g_slot_tok[off + m_g] * DIM;

    const int b_row = t >> 5;          // 0..7 (second half at +8)
    const int b_col = (t & 31) * 4;

    float accg[TM][TN], accu[TM][TN];
#pragma unroll
    for (int i = 0; i < TM; i++)
#pragma unroll
        for (int j = 0; j < TN; j++) { accg[i][j] = 0.f; accu[i][j] = 0.f; }

    for (int k0 = 0; k0 < DIM; k0 += BK) {
        float4 av  = *(const float4*)(a_src + k0 + a_seg * 4);
        float4 bg0 = *(const float4*)(Bg + (size_t)(k0 + b_row)     * FF + n0 + b_col);
        float4 bg1 = *(const float4*)(Bg + (size_t)(k0 + b_row + 8) * FF + n0 + b_col);
        float4 bu0 = *(const float4*)(Bu + (size_t)(k0 + b_row)     * FF + n0 + b_col);
        float4 bu1 = *(const float4*)(Bu + (size_t)(k0 + b_row + 8) * FF + n0 + b_col);
        __syncthreads();
        As[a_seg * 4 + 0][a_row] = av.x;
        As[a_seg * 4 + 1][a_row] = av.y;
        As[a_seg * 4 + 2][a_row] = av.z;
        As[a_seg * 4 + 3][a_row] = av.w;
        *(float4*)&Bgs[b_row][b_col]     = bg0;
        *(float4*)&Bgs[b_row + 8][b_col] = bg1;
        *(float4*)&Bus[b_row][b_col]     = bu0;
        *(float4*)&Bus[b_row + 8][b_col] = bu1;
        __syncthreads();
#pragma unroll
        for (int kk = 0; kk < BK; kk++) {
            float4 a4 = *(const float4*)&As[kk][tm0];
            float4 g0 = *(const float4*)&Bgs[kk][tn0];
            float4 g1 = *(const float4*)&Bgs[kk][tn0 + 4];
            float4 u0 = *(const float4*)&Bus[kk][tn0];
            float4 u1 = *(const float4*)&Bus[kk][tn0 + 4];
            float a_[TM] = {a4.x, a4.y, a4.z, a4.w};
            float gb[TN] = {g0.x, g0.y, g0.z, g0.w, g1.x, g1.y, g1.z, g1.w};
            float ub[TN] = {u0.x, u0.y, u0.z, u0.w, u1.x, u1.y, u1.z, u1.w};
#pragma unroll
            for (int i = 0; i < TM; i++)
#pragma unroll
                for (int j = 0; j < TN; j++) {
                    accg[i][j] = fmaf(a_[i], gb[j], accg[i][j]);
                    accu[i][j] = fmaf(a_[i], ub[j], accu[i][j]);
                }
        }
    }

#pragma unroll
    for (int i = 0; i < TM; i++) {
        int m = rowbase + tm0 + i;
        if (m < cnt) {
            int slot = off + m;
            float w = g_slot_w[slot];
            float* dst = g_act + (size_t)slot * FF + n0 + tn0;
#pragma unroll
            for (int j = 0; j < TN; j++) {
                float g = accg[i][j], u = accu[i][j];
                float s = g / (1.f + expf(-g));
                dst[j] = w * s * u;
            }
        }
    }
}

// ---------------------------------------------------------------------------
// Routed down GEMM: g_act[slot, FF] @ down_k[e] [FF, DIM] -> g_eo[tok*2+k, DIM]
// ---------------------------------------------------------------------------
__global__ __launch_bounds__(256)
void gemm_down_routed(const float* __restrict__ down_k)
{
    const int e = blockIdx.z;
    const int cnt = g_cnt[e];
    const int rowbase = blockIdx.y * BM;
    if (rowbase >= cnt) return;
    const int off = g_off[e];
    const int n0 = blockIdx.x * BN;
    const float* __restrict__ B = down_k + (size_t)e * FF * DIM;

    __shared__ float As[BK][68];
    __shared__ float Bs[BK][BN];

    const int t = threadIdx.x;
    const int tx = t & 15, ty = t >> 4;
    const int tn0 = tx * TN, tm0 = ty * TM;

    const int a_row = t >> 2, a_seg = t & 3;
    int m_g = rowbase + a_row;
    if (m_g >= cnt) m_g = cnt - 1;
    const float* a_src = g_act + (size_t)(off + m_g) * FF;

    const int b_row = t >> 5;
    const int b_col = (t & 31) * 4;

    float acc[TM][TN];
#pragma unroll
    for (int i = 0; i < TM; i++)
#pragma unroll
        for (int j = 0; j < TN; j++) acc[i][j] = 0.f;

    for (int k0 = 0; k0 < FF; k0 += BK) {
        float4 av = *(const float4*)(a_src + k0 + a_seg * 4);
        float4 b0 = *(const float4*)(B + (size_t)(k0 + b_row)     * DIM + n0 + b_col);
        float4 b1 = *(const float4*)(B + (size_t)(k0 + b_row + 8) * DIM + n0 + b_col);
        __syncthreads();
        As[a_seg * 4 + 0][a_row] = av.x;
        As[a_seg * 4 + 1][a_row] = av.y;
        As[a_seg * 4 + 2][a_row] = av.z;
        As[a_seg * 4 + 3][a_row] = av.w;
        *(float4*)&Bs[b_row][b_col]     = b0;
        *(float4*)&Bs[b_row + 8][b_col] = b1;
        __syncthreads();
#pragma unroll
        for (int kk = 0; kk < BK; kk++) {
            float4 a4 = *(const float4*)&As[kk][tm0];
            float4 c0 = *(const float4*)&Bs[kk][tn0];
            float4 c1 = *(const float4*)&Bs[kk][tn0 + 4];
            float a_[TM] = {a4.x, a4.y, a4.z, a4.w};
            float bb[TN] = {c0.x, c0.y, c0.z, c0.w, c1.x, c1.y, c1.z, c1.w};
#pragma unroll
            for (int i = 0; i < TM; i++)
#pragma unroll
                for (int j = 0; j < TN; j++)
                    acc[i][j] = fmaf(a_[i], bb[j], acc[i][j]);
        }
    }

#pragma unroll
    for (int i = 0; i < TM; i++) {
        int m = rowbase + tm0 + i;
        if (m < cnt) {
            int dst_row = g_slot_dst[off + m];
            float* dst = g_eo + (size_t)dst_row * DIM + n0 + tn0;
#pragma unroll
            for (int j = 0; j < TN; j++) dst[j] = acc[i][j];
        }
    }
}

// ---------------------------------------------------------------------------
// Shared expert gate+up fused GEMM + SwiGLU: x [NTOK, DIM] @ sh_gate/sh_up -> g_hs
// ---------------------------------------------------------------------------
__global__ __launch_bounds__(256)
void gemm_gateup_shared(const float* __restrict__ x,
                        const float* __restrict__ sh_gate,
                        const float* __restrict__ sh_up)
{
    const int rowbase = blockIdx.y * BM;
    const int n0 = blockIdx.x * BN;

    __shared__ float As[BK][68];
    __shared__ float Bgs[BK][BN];
    __shared__ float Bus[BK][BN];

    const int t = threadIdx.x;
    const int tx = t & 15, ty = t >> 4;
    const int tn0 = tx * TN, tm0 = ty * TM;

    const int a_row = t >> 2, a_seg = t & 3;
    const float* a_src = x + (size_t)(rowbase + a_row) * DIM;

    const int b_row = t >> 5;
    const int b_col = (t & 31) * 4;

    float accg[TM][TN], accu[TM][TN];
#pragma unroll
    for (int i = 0; i < TM; i++)
#pragma unroll
        for (int j = 0; j < TN; j++) { accg[i][j] = 0.f; accu[i][j] = 0.f; }

    for (int k0 = 0; k0 < DIM; k0 += BK) {
        float4 av  = *(const float4*)(a_src + k0 + a_seg * 4);
        float4 bg0 = *(const float4*)(sh_gate + (size_t)(k0 + b_row)     * FSH + n0 + b_col);
        float4 bg1 = *(const float4*)(sh_gate + (size_t)(k0 + b_row + 8) * FSH + n0 + b_col);
        float4 bu0 = *(const float4*)(sh_up   + (size_t)(k0 + b_row)     * FSH + n0 + b_col);
        float4 bu1 = *(const float4*)(sh_up   + (size_t)(k0 + b_row + 8) * FSH + n0 + b_col);
        __syncthreads();
        As[a_seg * 4 + 0][a_row] = av.x;
        As[a_seg * 4 + 1][a_row] = av.y;
        As[a_seg * 4 + 2][a_row] = av.z;
        As[a_seg * 4 + 3][a_row] = av.w;
        *(float4*)&Bgs[b_row][b_col]     = bg0;
        *(float4*)&Bgs[b_row + 8][b_col] = bg1;
        *(float4*)&Bus[b_row][b_col]     = bu0;
        *(float4*)&Bus[b_row + 8][b_col] = bu1;
        __syncthreads();
#pragma unroll
        for (int kk = 0; kk < BK; kk++) {
            float4 a4 = *(const float4*)&As[kk][tm0];
            float4 g0 = *(const float4*)&Bgs[kk][tn0];
            float4 g1 = *(const float4*)&Bgs[kk][tn0 + 4];
            float4 u0 = *(const float4*)&Bus[kk][tn0];
            float4 u1 = *(const float4*)&Bus[kk][tn0 + 4];
            float a_[TM] = {a4.x, a4.y, a4.z, a4.w};
            float gb[TN] = {g0.x, g0.y, g0.z, g0.w, g1.x, g1.y, g1.z, g1.w};
            float ub[TN] = {u0.x, u0.y, u0.z, u0.w, u1.x, u1.y, u1.z, u1.w};
#pragma unroll
            for (int i = 0; i < TM; i++)
#pragma unroll
                for (int j = 0; j < TN; j++) {
                    accg[i][j] = fmaf(a_[i], gb[j], accg[i][j]);
                    accu[i][j] = fmaf(a_[i], ub[j], accu[i][j]);
                }
        }
    }

#pragma unroll
    for (int i = 0; i < TM; i++) {
        int m = rowbase + tm0 + i;
        float* dst = g_hs + (size_t)m * FSH + n0 + tn0;
#pragma unroll
        for (int j = 0; j < TN; j++) {
            float g = accg[i][j], u = accu[i][j];
            float s = g / (1.f + expf(-g));
            dst[j] = s * u;
        }
    }
}

// ---------------------------------------------------------------------------
// Shared down GEMM + final combine:
// out[n, :] = g_hs[n] @ sh_down + g_eo[2n] + g_eo[2n+1]
// ---------------------------------------------------------------------------
__global__ __launch_bounds__(256)
void gemm_down_shared(const float* __restrict__ sh_down,
                      float* __restrict__ out)
{
    const int rowbase = blockIdx.y * BM;
    const int n0 = blockIdx.x * BN;

    __shared__ float As[BK][68];
    __shared__ float Bs[BK][BN];

    const int t = threadIdx.x;
    const int tx = t & 15, ty = t >> 4;
    const int tn0 = tx * TN, tm0 = ty * TM;

    const int a_row = t >> 2, a_seg = t & 3;
    const float* a_src = g_hs + (size_t)(rowbase + a_row) * FSH;

    const int b_row = t >> 5;
    const int b_col = (t & 31) * 4;

    float acc[TM][TN];
#pragma unroll
    for (int i = 0; i < TM; i++)
#pragma unroll
        for (int j = 0; j < TN; j++) acc[i][j] = 0.f;

    for (int k0 = 0; k0 < FSH; k0 += BK) {
        float4 av = *(const float4*)(a_src + k0 + a_seg * 4);
        float4 b0 = *(const float4*)(sh_down + (size_t)(k0 + b_row)     * DIM + n0 + b_col);
        float4 b1 = *(const float4*)(sh_down + (size_t)(k0 + b_row + 8) * DIM + n0 + b_col);
        __syncthreads();
        As[a_seg * 4 + 0][a_row] = av.x;
        As[a_seg * 4 + 1][a_row] = av.y;
        As[a_seg * 4 + 2][a_row] = av.z;
        As[a_seg * 4 + 3][a_row] = av.w;
        *(float4*)&Bs[b_row][b_col]     = b0;
        *(float4*)&Bs[b_row + 8][b_col] = b1;
        __syncthreads();
#pragma unroll
        for (int kk = 0; kk < BK; kk++) {
            float4 a4 = *(const float4*)&As[kk][tm0];
            float4 c0 = *(const float4*)&Bs[kk][tn0];
            float4 c1 = *(const float4*)&Bs[kk][tn0 + 4];
            float a_[TM] = {a4.x, a4.y, a4.z, a4.w};
            float bb[TN] = {c0.x, c0.y, c0.z, c0.w, c1.x, c1.y, c1.z, c1.w};
#pragma unroll
            for (int i = 0; i < TM; i++)
#pragma unroll
                for (int j = 0; j < TN; j++)
                    acc[i][j] = fmaf(a_[i], bb[j], acc[i][j]);
        }
    }

#pragma unroll
    for (int i = 0; i < TM; i++) {
        int m = rowbase + tm0 + i;
        const float* eo0 = g_eo + (size_t)(m * 2)     * DIM + n0 + tn0;
        const float* eo1 = g_eo + (size_t)(m * 2 + 1) * DIM + n0 + tn0;
        float* dst = out + (size_t)m * DIM + n0 + tn0;
#pragma unroll
        for (int j = 0; j < TN; j++)
            dst[j] = acc[i][j] + eo0[j] + eo1[j];
    }
}

// ---------------------------------------------------------------------------
extern "C" void kernel_launch(void* const* d_in, const int* in_sizes, int n_in,
                              void* d_out, int out_size)
{
    const float* x       = (const float*)d_in[0];
    const float* gate_w  = (const float*)d_in[1];
    const float* gate_k  = (const float*)d_in[2];
    const float* up_k    = (const float*)d_in[3];
    const float* down_k  = (const float*)d_in[4];
    const float* sh_gate = (const float*)d_in[5];
    const float* sh_up   = (const float*)d_in[6];
    const float* sh_down = (const float*)d_in[7];
    float* out = (float*)d_out;

    zero_cnt_kernel<<<1, 32>>>();
    router_kernel<<<NTOK, 128>>>(x, gate_w);
    scan_kernel<<<1, 32>>>();
    fill_kernel<<<NTOK / 256, 256>>>();

    gemm_gateup_routed<<<dim3(FF / BN, NTOK / BM, NE), 256>>>(x, gate_k, up_k);
    gemm_down_routed<<<dim3(DIM / BN, NTOK / BM, NE), 256>>>(down_k);
    gemm_gateup_shared<<<dim3(FSH / BN, NTOK / BM), 256>>>(x, sh_gate, sh_up);
    gemm_down_shared<<<dim3(DIM / BN, NTOK / BM), 256>>>(sh_down, out);
}

// round 2
// speedup vs baseline: 3.1124x; 3.1124x over previous
#include <cuda_runtime.h>
#include <math.h>
#include <stdint.h>

// Problem constants
#define NTOK 2048
#define DIM  1024
#define FF   4096
#define FSH  2048
#define NE   8
#define TOPK 2
#define NSLOT (NTOK*TOPK)

// GEMM tiling (tensor-core version)
#define BM 128
#define BN 64
#define BK 32
#define APAD 8
#define BPAD 8
// 256 threads = 8 warps in 4(M) x 2(N); warp tile 32x32 = 2 mtiles x 4 ntiles of m16n8k8

// ---- scratch ----
__device__ float g_act[(size_t)NSLOT * FF];
__device__ float g_eo[(size_t)NSLOT * DIM];
__device__ float g_hs[(size_t)NTOK * FSH];
__device__ float g_topw[NTOK * TOPK];
__device__ int   g_topi[NTOK * TOPK];
__device__ int   g_slot_tok[NSLOT];
__device__ float g_slot_w[NSLOT];
__device__ int   g_slot_dst[NSLOT];
__device__ int   g_cnt[NE];
__device__ int   g_off[NE + 1];

// ---------------------------------------------------------------------------
__device__ __forceinline__ uint32_t f2tf32(float x) {
    uint32_t r;
    asm("cvt.rna.tf32.f32 %0, %1;" : "=r"(r) : "f"(x));
    return r;
}

__device__ __forceinline__ void mma_tf32(float& c0, float& c1, float& c2, float& c3,
                                         uint32_t a0, uint32_t a1, uint32_t a2, uint32_t a3,
                                         uint32_t b0, uint32_t b1)
{
    asm volatile(
        "mma.sync.aligned.m16n8k8.row.col.f32.tf32.tf32.f32 "
        "{%0,%1,%2,%3},{%4,%5,%6,%7},{%8,%9},{%0,%1,%2,%3};"
        : "+f"(c0), "+f"(c1), "+f"(c2), "+f"(c3)
        : "r"(a0), "r"(a1), "r"(a2), "r"(a3), "r"(b0), "r"(b1));
}

// ---------------------------------------------------------------------------
// Router (unchanged from R1)
// ---------------------------------------------------------------------------
__global__ void router_kernel(const float* __restrict__ x,
                              const float* __restrict__ gate_w)
{
    const int n = blockIdx.x;
    const int tid = threadIdx.x;
    __shared__ float sred[NE][128];

    float acc[NE];
#pragma unroll
    for (int e = 0; e < NE; e++) acc[e] = 0.f;

    const float* xr = x + (size_t)n * DIM;
    for (int d = tid; d < DIM; d += 128) {
        float xv = xr[d];
#pragma unroll
        for (int e = 0; e < NE; e++)
            acc[e] = fmaf(xv, gate_w[e * DIM + d], acc[e]);
    }
#pragma unroll
    for (int e = 0; e < NE; e++) sred[e][tid] = acc[e];
    __syncthreads();

    if (tid < NE) {
        float s = 0.f;
        for (int i = 0; i < 128; i++) s += sred[tid][i];
        sred[tid][0] = s;
    }
    __syncthreads();

    if (tid == 0) {
        float lg[NE];
#pragma unroll
        for (int e = 0; e < NE; e++) lg[e] = sred[e][0];
        float mx = lg[0];
#pragma unroll
        for (int e = 1; e < NE; e++) mx = fmaxf(mx, lg[e]);
        float se = 0.f, p[NE];
#pragma unroll
        for (int e = 0; e < NE; e++) { p[e] = expf(lg[e] - mx); se += p[e]; }
        float inv = 1.f / se;
#pragma unroll
        for (int e = 0; e < NE; e++) p[e] *= inv;

        int i1 = 0; float v1 = p[0];
#pragma unroll
        for (int e = 1; e < NE; e++) if (p[e] > v1) { v1 = p[e]; i1 = e; }
        int i2 = -1; float v2 = -1.f;
#pragma unroll
        for (int e = 0; e < NE; e++) if (e != i1 && p[e] > v2) { v2 = p[e]; i2 = e; }

        g_topi[n * 2 + 0] = i1;  g_topw[n * 2 + 0] = v1;
        g_topi[n * 2 + 1] = i2;  g_topw[n * 2 + 1] = v2;
        atomicAdd(&g_cnt[i1], 1);
        atomicAdd(&g_cnt[i2], 1);
    }
}

__global__ void zero_cnt_kernel()
{
    if (threadIdx.x < NE) g_cnt[threadIdx.x] = 0;
}

__global__ void scan_kernel()
{
    if (threadIdx.x == 0) {
        int r = 0;
        for (int e = 0; e < NE; e++) { g_off[e] = r; r += g_cnt[e]; g_cnt[e] = 0; }
        g_off[NE] = r;
    }
}

__global__ void fill_kernel()
{
    int n = blockIdx.x * blockDim.x + threadIdx.x;
    if (n >= NTOK) return;
#pragma unroll
    for (int k = 0; k < TOPK; k++) {
        int e = g_topi[n * 2 + k];
        int pos = atomicAdd(&g_cnt[e], 1);
        int slot = g_off[e] + pos;
        g_slot_tok[slot] = n;
        g_slot_w[slot]   = g_topw[n * 2 + k];
        g_slot_dst[slot] = n * 2 + k;
    }
}

// ---------------------------------------------------------------------------
// Shared helpers: store a BKxBM A tile (transposed, tf32-rounded) and BKxBN B
// tiles. All compute kernels share the same thread->data mapping:
//   A: thread t loads row (t>>1), k segment (t&1)*16, 4x float4
//   B: thread t loads k-row (t>>3), col (t&7)*8, 2x float4
// ---------------------------------------------------------------------------

// Fragment/epilogue lane decomposition
#define LANE_Q (lane >> 2)
#define LANE_R (lane & 3)

// ---------------------------------------------------------------------------
// Routed gate+up fused GEMM (tf32 mma) + SwiGLU + routing weight
// ---------------------------------------------------------------------------
__global__ __launch_bounds__(256)
void gemm_gateup_routed(const float* __restrict__ x,
                        const float* __restrict__ gate_k,
                        const float* __restrict__ up_k)
{
    const int e = blockIdx.z;
    const int cnt = g_cnt[e];
    const int rowbase = blockIdx.y * BM;
    if (rowbase >= cnt) return;
    const int off = g_off[e];
    const int n0 = blockIdx.x * BN;
    const float* __restrict__ Bg = gate_k + (size_t)e * DIM * FF;
    const float* __restrict__ Bu = up_k   + (size_t)e * DIM * FF;

    __shared__ float As[BK][BM + APAD];
    __shared__ float Bgs[BK][BN + BPAD];
    __shared__ float Bus[BK][BN + BPAD];

    const int t = threadIdx.x;
    const int wid = t >> 5, lane = t & 31;
    const int wm = (wid >> 1) * 32;           // warp M offset (4 warps in M)
    const int wn = (wid & 1) * 32;            // warp N offset (2 warps in N)

    // A gather
    const int a_row = t >> 1, a_k0 = (t & 1) * 16;
    int m_g = rowbase + a_row;
    if (m_g >= cnt) m_g = cnt - 1;
    const float* a_src = x + (size_t)g_slot_tok[off + m_g] * DIM;

    // B load
    const int b_row = t >> 3, b_col = (t & 7) * 8;

    float accg[2][4][4], accu[2][4][4];
#pragma unroll
    for (int i = 0; i < 2; i++)
#pragma unroll
        for (int j = 0; j < 4; j++)
#pragma unroll
            for (int c = 0; c < 4; c++) { accg[i][j][c] = 0.f; accu[i][j][c] = 0.f; }

    for (int k0 = 0; k0 < DIM; k0 += BK) {
        float4 av[4];
#pragma unroll
        for (int l = 0; l < 4; l++)
            av[l] = *(const float4*)(a_src + k0 + a_k0 + l * 4);
        float4 bg0 = *(const float4*)(Bg + (size_t)(k0 + b_row) * FF + n0 + b_col);
        float4 bg1 = *(const float4*)(Bg + (size_t)(k0 + b_row) * FF + n0 + b_col + 4);
        float4 bu0 = *(const float4*)(Bu + (size_t)(k0 + b_row) * FF + n0 + b_col);
        float4 bu1 = *(const float4*)(Bu + (size_t)(k0 + b_row) * FF + n0 + b_col + 4);
        __syncthreads();
#pragma unroll
        for (int l = 0; l < 4; l++) {
            int kk = a_k0 + l * 4;
            As[kk + 0][a_row] = __uint_as_float(f2tf32(av[l].x));
            As[kk + 1][a_row] = __uint_as_float(f2tf32(av[l].y));
            As[kk + 2][a_row] = __uint_as_float(f2tf32(av[l].z));
            As[kk + 3][a_row] = __uint_as_float(f2tf32(av[l].w));
        }
        {
            float4 r0 = make_float4(__uint_as_float(f2tf32(bg0.x)), __uint_as_float(f2tf32(bg0.y)),
                                    __uint_as_float(f2tf32(bg0.z)), __uint_as_float(f2tf32(bg0.w)));
            float4 r1 = make_float4(__uint_as_float(f2tf32(bg1.x)), __uint_as_float(f2tf32(bg1.y)),
                                    __uint_as_float(f2tf32(bg1.z)), __uint_as_float(f2tf32(bg1.w)));
            *(float4*)&Bgs[b_row][b_col]     = r0;
            *(float4*)&Bgs[b_row][b_col + 4] = r1;
            float4 r2 = make_float4(__uint_as_float(f2tf32(bu0.x)), __uint_as_float(f2tf32(bu0.y)),
                                    __uint_as_float(f2tf32(bu0.z)), __uint_as_float(f2tf32(bu0.w)));
            float4 r3 = make_float4(__uint_as_float(f2tf32(bu1.x)), __uint_as_float(f2tf32(bu1.y)),
                                    __uint_as_float(f2tf32(bu1.z)), __uint_as_float(f2tf32(bu1.w)));
            *(float4*)&Bus[b_row][b_col]     = r2;
            *(float4*)&Bus[b_row][b_col + 4] = r3;
        }
        __syncthreads();

#pragma unroll
        for (int ks = 0; ks < 4; ks++) {
            const int kb = ks * 8;
            uint32_t af[2][4];
#pragma unroll
            for (int mt = 0; mt < 2; mt++) {
                int mr = wm + mt * 16 + LANE_Q;
                af[mt][0] = __float_as_uint(As[kb + LANE_R][mr]);
                af[mt][1] = __float_as_uint(As[kb + LANE_R][mr + 8]);
                af[mt][2] = __float_as_uint(As[kb + 4 + LANE_R][mr]);
                af[mt][3] = __float_as_uint(As[kb + 4 + LANE_R][mr + 8]);
            }
            uint32_t bgf[4][2], buf[4][2];
#pragma unroll
            for (int nt = 0; nt < 4; nt++) {
                int nc = wn + nt * 8 + LANE_Q;
                bgf[nt][0] = __float_as_uint(Bgs[kb + LANE_R][nc]);
                bgf[nt][1] = __float_as_uint(Bgs[kb + 4 + LANE_R][nc]);
                buf[nt][0] = __float_as_uint(Bus[kb + LANE_R][nc]);
                buf[nt][1] = __float_as_uint(Bus[kb + 4 + LANE_R][nc]);
            }
#pragma unroll
            for (int mt = 0; mt < 2; mt++)
#pragma unroll
                for (int nt = 0; nt < 4; nt++) {
                    mma_tf32(accg[mt][nt][0], accg[mt][nt][1], accg[mt][nt][2], accg[mt][nt][3],
                             af[mt][0], af[mt][1], af[mt][2], af[mt][3], bgf[nt][0], bgf[nt][1]);
                    mma_tf32(accu[mt][nt][0], accu[mt][nt][1], accu[mt][nt][2], accu[mt][nt][3],
                             af[mt][0], af[mt][1], af[mt][2], af[mt][3], buf[nt][0], buf[nt][1]);
                }
        }
    }

    // epilogue: silu(g)*u * w -> g_act[slot][n0+col]
#pragma unroll
    for (int mt = 0; mt < 2; mt++) {
        int r0 = wm + mt * 16 + LANE_Q;
#pragma unroll
        for (int half = 0; half < 2; half++) {
            int m = rowbase + r0 + half * 8;
            if (m < cnt) {
                int slot = off + m;
                float w = g_slot_w[slot];
                float* dst = g_act + (size_t)slot * FF + n0;
#pragma unroll
                for (int nt = 0; nt < 4; nt++) {
                    int cb = wn + nt * 8 + 2 * LANE_R;
                    float gv0 = accg[mt][nt][half * 2 + 0];
                    float gv1 = accg[mt][nt][half * 2 + 1];
                    float uv0 = accu[mt][nt][half * 2 + 0];
                    float uv1 = accu[mt][nt][half * 2 + 1];
                    dst[cb]     = w * (gv0 / (1.f + expf(-gv0))) * uv0;
                    dst[cb + 1] = w * (gv1 / (1.f + expf(-gv1))) * uv1;
                }
            }
        }
    }
}

// ---------------------------------------------------------------------------
// Routed down GEMM (tf32 mma): g_act[slot,FF] @ down_k[e][FF,DIM] -> g_eo
// ---------------------------------------------------------------------------
__global__ __launch_bounds__(256)
void gemm_down_routed(const float* __restrict__ down_k)
{
    const int e = blockIdx.z;
    const int cnt = g_cnt[e];
    const int rowbase = blockIdx.y * BM;
    if (rowbase >= cnt) return;
    const int off = g_off[e];
    const int n0 = blockIdx.x * BN;
    const float* __restrict__ B = down_k + (size_t)e * FF * DIM;

    __shared__ float As[BK][BM + APAD];
    __shared__ float Bs[BK][BN + BPAD];

    const int t = threadIdx.x;
    const int wid = t >> 5, lane = t & 31;
    const int wm = (wid >> 1) * 32;
    const int wn = (wid & 1) * 32;

    const int a_row = t >> 1, a_k0 = (t & 1) * 16;
    int m_g = rowbase + a_row;
    if (m_g >= cnt) m_g = cnt - 1;
    const float* a_src = g_act + (size_t)(off + m_g) * FF;

    const int b_row = t >> 3, b_col = (t & 7) * 8;

    float acc[2][4][4];
#pragma unroll
    for (int i = 0; i < 2; i++)
#pragma unroll
        for (int j = 0; j < 4; j++)
#pragma unroll
            for (int c = 0; c < 4; c++) acc[i][j][c] = 0.f;

    for (int k0 = 0; k0 < FF; k0 += BK) {
        float4 av[4];
#pragma unroll
        for (int l = 0; l < 4; l++)
            av[l] = *(const float4*)(a_src + k0 + a_k0 + l * 4);
        float4 b0 = *(const float4*)(B + (size_t)(k0 + b_row) * DIM + n0 + b_col);
        float4 b1 = *(const float4*)(B + (size_t)(k0 + b_row) * DIM + n0 + b_col + 4);
        __syncthreads();
#pragma unroll
        for (int l = 0; l < 4; l++) {
            int kk = a_k0 + l * 4;
            As[kk + 0][a_row] = __uint_as_float(f2tf32(av[l].x));
            As[kk + 1][a_row] = __uint_as_float(f2tf32(av[l].y));
            As[kk + 2][a_row] = __uint_as_float(f2tf32(av[l].z));
            As[kk + 3][a_row] = __uint_as_float(f2tf32(av[l].w));
        }
        {
            float4 r0 = make_float4(__uint_as_float(f2tf32(b0.x)), __uint_as_float(f2tf32(b0.y)),
                                    __uint_as_float(f2tf32(b0.z)), __uint_as_float(f2tf32(b0.w)));
            float4 r1 = make_float4(__uint_as_float(f2tf32(b1.x)), __uint_as_float(f2tf32(b1.y)),
                                    __uint_as_float(f2tf32(b1.z)), __uint_as_float(f2tf32(b1.w)));
            *(float4*)&Bs[b_row][b_col]     = r0;
            *(float4*)&Bs[b_row][b_col + 4] = r1;
        }
        __syncthreads();

#pragma unroll
        for (int ks = 0; ks < 4; ks++) {
            const int kb = ks * 8;
            uint32_t af[2][4];
#pragma unroll
            for (int mt = 0; mt < 2; mt++) {
                int mr = wm + mt * 16 + LANE_Q;
                af[mt][0] = __float_as_uint(As[kb + LANE_R][mr]);
                af[mt][1] = __float_as_uint(As[kb + LANE_R][mr + 8]);
                af[mt][2] = __float_as_uint(As[kb + 4 + LANE_R][mr]);
                af[mt][3] = __float_as_uint(As[kb + 4 + LANE_R][mr + 8]);
            }
            uint32_t bf[4][2];
#pragma unroll
            for (int nt = 0; nt < 4; nt++) {
                int nc = wn + nt * 8 + LANE_Q;
                bf[nt][0] = __float_as_uint(Bs[kb + LANE_R][nc]);
                bf[nt][1] = __float_as_uint(Bs[kb + 4 + LANE_R][nc]);
            }
#pragma unroll
            for (int mt = 0; mt < 2; mt++)
#pragma unroll
                for (int nt = 0; nt < 4; nt++)
                    mma_tf32(acc[mt][nt][0], acc[mt][nt][1], acc[mt][nt][2], acc[mt][nt][3],
                             af[mt][0], af[mt][1], af[mt][2], af[mt][3], bf[nt][0], bf[nt][1]);
        }
    }

#pragma unroll
    for (int mt = 0; mt < 2; mt++) {
        int r0 = wm + mt * 16 + LANE_Q;
#pragma unroll
        for (int half = 0; half < 2; half++) {
            int m = rowbase + r0 + half * 8;
            if (m < cnt) {
                int dst_row = g_slot_dst[off + m];
                float* dst = g_eo + (size_t)dst_row * DIM + n0;
#pragma unroll
                for (int nt = 0; nt < 4; nt++) {
                    int cb = wn + nt * 8 + 2 * LANE_R;
                    dst[cb]     = acc[mt][nt][half * 2 + 0];
                    dst[cb + 1] = acc[mt][nt][half * 2 + 1];
                }
            }
        }
    }
}

// ---------------------------------------------------------------------------
// Shared expert gate+up (tf32 mma) + SwiGLU
// ---------------------------------------------------------------------------
__global__ __launch_bounds__(256)
void gemm_gateup_shared(const float* __restrict__ x,
                        const float* __restrict__ sh_gate,
                        const float* __restrict__ sh_up)
{
    const int rowbase = blockIdx.y * BM;
    const int n0 = blockIdx.x * BN;

    __shared__ float As[BK][BM + APAD];
    __shared__ float Bgs[BK][BN + BPAD];
    __shared__ float Bus[BK][BN + BPAD];

    const int t = threadIdx.x;
    const int wid = t >> 5, lane = t & 31;
    const int wm = (wid >> 1) * 32;
    const int wn = (wid & 1) * 32;

    const int a_row = t >> 1, a_k0 = (t & 1) * 16;
    const float* a_src = x + (size_t)(rowbase + a_row) * DIM;

    const int b_row = t >> 3, b_col = (t & 7) * 8;

    float accg[2][4][4], accu[2][4][4];
#pragma unroll
    for (int i = 0; i < 2; i++)
#pragma unroll
        for (int j = 0; j < 4; j++)
#pragma unroll
            for (int c = 0; c < 4; c++) { accg[i][j][c] = 0.f; accu[i][j][c] = 0.f; }

    for (int k0 = 0; k0 < DIM; k0 += BK) {
        float4 av[4];
#pragma unroll
        for (int l = 0; l < 4; l++)
            av[l] = *(const float4*)(a_src + k0 + a_k0 + l * 4);
        float4 bg0 = *(const float4*)(sh_gate + (size_t)(k0 + b_row) * FSH + n0 + b_col);
        float4 bg1 = *(const float4*)(sh_gate + (size_t)(k0 + b_row) * FSH + n0 + b_col + 4);
        float4 bu0 = *(const float4*)(sh_up   + (size_t)(k0 + b_row) * FSH + n0 + b_col);
        float4 bu1 = *(const float4*)(sh_up   + (size_t)(k0 + b_row) * FSH + n0 + b_col + 4);
        __syncthreads();
#pragma unroll
        for (int l = 0; l < 4; l++) {
            int kk = a_k0 + l * 4;
            As[kk + 0][a_row] = __uint_as_float(f2tf32(av[l].x));
            As[kk + 1][a_row] = __uint_as_float(f2tf32(av[l].y));
            As[kk + 2][a_row] = __uint_as_float(f2tf32(av[l].z));
            As[kk + 3][a_row] = __uint_as_float(f2tf32(av[l].w));
        }
        {
            float4 r0 = make_float4(__uint_as_float(f2tf32(bg0.x)), __uint_as_float(f2tf32(bg0.y)),
                                    __uint_as_float(f2tf32(bg0.z)), __uint_as_float(f2tf32(bg0.w)));
            float4 r1 = make_float4(__uint_as_float(f2tf32(bg1.x)), __uint_as_float(f2tf32(bg1.y)),
                                    __uint_as_float(f2tf32(bg1.z)), __uint_as_float(f2tf32(bg1.w)));
            *(float4*)&Bgs[b_row][b_col]     = r0;
            *(float4*)&Bgs[b_row][b_col + 4] = r1;
            float4 r2 = make_float4(__uint_as_float(f2tf32(bu0.x)), __uint_as_float(f2tf32(bu0.y)),
                                    __uint_as_float(f2tf32(bu0.z)), __uint_as_float(f2tf32(bu0.w)));
            float4 r3 = make_float4(__uint_as_float(f2tf32(bu1.x)), __uint_as_float(f2tf32(bu1.y)),
                                    __uint_as_float(f2tf32(bu1.z)), __uint_as_float(f2tf32(bu1.w)));
            *(float4*)&Bus[b_row][b_col]     = r2;
            *(float4*)&Bus[b_row][b_col + 4] = r3;
        }
        __syncthreads();

#pragma unroll
        for (int ks = 0; ks < 4; ks++) {
            const int kb = ks * 8;
            uint32_t af[2][4];
#pragma unroll
            for (int mt = 0; mt < 2; mt++) {
                int mr = wm + mt * 16 + LANE_Q;
                af[mt][0] = __float_as_uint(As[kb + LANE_R][mr]);
                af[mt][1] = __float_as_uint(As[kb + LANE_R][mr + 8]);
                af[mt][2] = __float_as_uint(As[kb + 4 + LANE_R][mr]);
                af[mt][3] = __float_as_uint(As[kb + 4 + LANE_R][mr + 8]);
            }
            uint32_t bgf[4][2], buf[4][2];
#pragma unroll
            for (int nt = 0; nt < 4; nt++) {
                int nc = wn + nt * 8 + LANE_Q;
                bgf[nt][0] = __float_as_uint(Bgs[kb + LANE_R][nc]);
                bgf[nt][1] = __float_as_uint(Bgs[kb + 4 + LANE_R][nc]);
                buf[nt][0] = __float_as_uint(Bus[kb + LANE_R][nc]);
                buf[nt][1] = __float_as_uint(Bus[kb + 4 + LANE_R][nc]);
            }
#pragma unroll
            for (int mt = 0; mt < 2; mt++)
#pragma unroll
                for (int nt = 0; nt < 4; nt++) {
                    mma_tf32(accg[mt][nt][0], accg[mt][nt][1], accg[mt][nt][2], accg[mt][nt][3],
                             af[mt][0], af[mt][1], af[mt][2], af[mt][3], bgf[nt][0], bgf[nt][1]);
                    mma_tf32(accu[mt][nt][0], accu[mt][nt][1], accu[mt][nt][2], accu[mt][nt][3],
                             af[mt][0], af[mt][1], af[mt][2], af[mt][3], buf[nt][0], buf[nt][1]);
                }
        }
    }

#pragma unroll
    for (int mt = 0; mt < 2; mt++) {
        int r0 = wm + mt * 16 + LANE_Q;
#pragma unroll
        for (int half = 0; half < 2; half++) {
            int m = rowbase + r0 + half * 8;
            float* dst = g_hs + (size_t)m * FSH + n0;
#pragma unroll
            for (int nt = 0; nt < 4; nt++) {
                int cb = wn + nt * 8 + 2 * LANE_R;
                float gv0 = accg[mt][nt][half * 2 + 0];
                float gv1 = accg[mt][nt][half * 2 + 1];
                float uv0 = accu[mt][nt][half * 2 + 0];
                float uv1 = accu[mt][nt][half * 2 + 1];
                dst[cb]     = (gv0 / (1.f + expf(-gv0))) * uv0;
                dst[cb + 1] = (gv1 / (1.f + expf(-gv1))) * uv1;
            }
        }
    }
}

// ---------------------------------------------------------------------------
// Shared down GEMM (tf32 mma) + final combine
// ---------------------------------------------------------------------------
__global__ __launch_bounds__(256)
void gemm_down_shared(const float* __restrict__ sh_down,
                      float* __restrict__ out)
{
    const int rowbase = blockIdx.y * BM;
    const int n0 = blockIdx.x * BN;

    __shared__ float As[BK][BM + APAD];
    __shared__ float Bs[BK][BN + BPAD];

    const int t = threadIdx.x;
    const int wid = t >> 5, lane = t & 31;
    const int wm = (wid >> 1) * 32;
    const int wn = (wid & 1) * 32;

    const int a_row = t >> 1, a_k0 = (t & 1) * 16;
    const float* a_src = g_hs + (size_t)(rowbase + a_row) * FSH;

    const int b_row = t >> 3, b_col = (t & 7) * 8;

    float acc[2][4][4];
#pragma unroll
    for (int i = 0; i < 2; i++)
#pragma unroll
        for (int j = 0; j < 4; j++)
#pragma unroll
            for (int c = 0; c < 4; c++) acc[i][j][c] = 0.f;

    for (int k0 = 0; k0 < FSH; k0 += BK) {
        float4 av[4];
#pragma unroll
        for (int l = 0; l < 4; l++)
            av[l] = *(const float4*)(a_src + k0 + a_k0 + l * 4);
        float4 b0 = *(const float4*)(sh_down + (size_t)(k0 + b_row) * DIM + n0 + b_col);
        float4 b1 = *(const float4*)(sh_down + (size_t)(k0 + b_row) * DIM + n0 + b_col + 4);
        __syncthreads();
#pragma unroll
        for (int l = 0; l < 4; l++) {
            int kk = a_k0 + l * 4;
            As[kk + 0][a_row] = __uint_as_float(f2tf32(av[l].x));
            As[kk + 1][a_row] = __uint_as_float(f2tf32(av[l].y));
            As[kk + 2][a_row] = __uint_as_float(f2tf32(av[l].z));
            As[kk + 3][a_row] = __uint_as_float(f2tf32(av[l].w));
        }
        {
            float4 r0 = make_float4(__uint_as_float(f2tf32(b0.x)), __uint_as_float(f2tf32(b0.y)),
                                    __uint_as_float(f2tf32(b0.z)), __uint_as_float(f2tf32(b0.w)));
            float4 r1 = make_float4(__uint_as_float(f2tf32(b1.x)), __uint_as_float(f2tf32(b1.y)),
                                    __uint_as_float(f2tf32(b1.z)), __uint_as_float(f2tf32(b1.w)));
            *(float4*)&Bs[b_row][b_col]     = r0;
            *(float4*)&Bs[b_row][b_col + 4] = r1;
        }
        __syncthreads();

#pragma unroll
        for (int ks = 0; ks < 4; ks++) {
            const int kb = ks * 8;
            uint32_t af[2][4];
#pragma unroll
            for (int mt = 0; mt < 2; mt++) {
                int mr = wm + mt * 16 + LANE_Q;
                af[mt][0] = __float_as_uint(As[kb + LANE_R][mr]);
                af[mt][1] = __float_as_uint(As[kb + LANE_R][mr + 8]);
                af[mt][2] = __float_as_uint(As[kb + 4 + LANE_R][mr]);
                af[mt][3] = __float_as_uint(As[kb + 4 + LANE_R][mr + 8]);
            }
            uint32_t bf[4][2];
#pragma unroll
            for (int nt = 0; nt < 4; nt++) {
                int nc = wn + nt * 8 + LANE_Q;
                bf[nt][0] = __float_as_uint(Bs[kb + LANE_R][nc]);
                bf[nt][1] = __float_as_uint(Bs[kb + 4 + LANE_R][nc]);
            }
#pragma unroll
            for (int mt = 0; mt < 2; mt++)
#pragma unroll
                for (int nt = 0; nt < 4; nt++)
                    mma_tf32(acc[mt][nt][0], acc[mt][nt][1], acc[mt][nt][2], acc[mt][nt][3],
                             af[mt][0], af[mt][1], af[mt][2], af[mt][3], bf[nt][0], bf[nt][1]);
        }
    }

#pragma unroll
    for (int mt = 0; mt < 2; mt++) {
        int r0 = wm + mt * 16 + LANE_Q;
#pragma unroll
        for (int half = 0; half < 2; half++) {
            int m = rowbase + r0 + half * 8;
            const float* eo0 = g_eo + (size_t)(m * 2)     * DIM + n0;
            const float* eo1 = g_eo + (size_t)(m * 2 + 1) * DIM + n0;
            float* dst = out + (size_t)m * DIM + n0;
#pragma unroll
            for (int nt = 0; nt < 4; nt++) {
                int cb = wn + nt * 8 + 2 * LANE_R;
                dst[cb]     = acc[mt][nt][half * 2 + 0] + eo0[cb]     + eo1[cb];
                dst[cb + 1] = acc[mt][nt][half * 2 + 1] + eo0[cb + 1] + eo1[cb + 1];
            }
        }
    }
}

// ---------------------------------------------------------------------------
extern "C" void kernel_launch(void* const* d_in, const int* in_sizes, int n_in,
                              void* d_out, int out_size)
{
    const float* x       = (const float*)d_in[0];
    const float* gate_w  = (const float*)d_in[1];
    const float* gate_k  = (const float*)d_in[2];
    const float* up_k    = (const float*)d_in[3];
    const float* down_k  = (const float*)d_in[4];
    const float* sh_gate = (const float*)d_in[5];
    const float* sh_up   = (const float*)d_in[6];
    const float* sh_down = (const float*)d_in[7];
    float* out = (float*)d_out;

    zero_cnt_kernel<<<1, 32>>>();
    router_kernel<<<NTOK, 128>>>(x, gate_w);
    scan_kernel<<<1, 32>>>();
    fill_kernel<<<NTOK / 256, 256>>>();

    gemm_gateup_routed<<<dim3(FF / BN, NTOK / BM, NE), 256>>>(x, gate_k, up_k);
    gemm_down_routed<<<dim3(DIM / BN, NTOK / BM, NE), 256>>>(down_k);
    gemm_gateup_shared<<<dim3(FSH / BN, NTOK / BM), 256>>>(x, sh_gate, sh_up);
    gemm_down_shared<<<dim3(DIM / BN, NTOK / BM), 256>>>(sh_down, out);
}